// round 6
// baseline (speedup 1.0000x reference)
#include <cuda_runtime.h>
#include <cuda_bf16.h>
#include <cstdint>

#define Nb 8
#define LL 4096
#define SS 4096
#define EE 256
#define HH 8
#define DD 32
#define NTOK (Nb*LL)
#define EPSV 1e-6f
#define NCHUNK 8
#define CHS (SS/NCHUNK)

typedef unsigned short ushortT;

// ---------------- scratch (device globals; no dynamic alloc) ----------------
__device__ float g_Qf[NTOK*EE];        // feature-mapped Q  (32 MB)
__device__ float g_Kf[Nb*SS*EE];       // feature-mapped K  (32 MB)
__device__ float g_Vm[Nb*SS*EE];       // masked V / S      (32 MB)
__device__ float g_part[NCHUNK*Nb*HH*1056]; // partial KV+Ksum
__device__ float g_KV[Nb*HH*1056];     // [d*32+v] then Ksum at 1024+d
__device__ float g_UT[Nb*EE*EE];       // U^T[n][e'][h*32+d]
__device__ float g_Z[NTOK*HH];         // normalizer per (row, h)
__device__ int   g_mask_kind;          // 0=u8 1=i32 2=f32 3=bf16
// pre-split B matrices (hi/lo bf16, tiled in the exact smem/ldmatrix layout)
#define MATU 147456                    // ushorts per 256x256 split matrix
__device__ ushortT g_Wsp[3*MATU];      // Wq, Wk, Wv
__device__ ushortT g_UTsp[Nb*MATU];    // per-batch UT

// ---------------- helpers ----------------
__device__ __forceinline__ uint32_t smem_u32(const void* p) {
    uint32_t a;
    asm("{ .reg .u64 t; cvta.to.shared.u64 t, %1; cvt.u32.u64 %0, t; }" : "=r"(a) : "l"(p));
    return a;
}
__device__ __forceinline__ void ldsm4(unsigned* r, uint32_t addr) {
    asm volatile("ldmatrix.sync.aligned.m8n8.x4.shared.b16 {%0,%1,%2,%3}, [%4];"
        : "=r"(r[0]), "=r"(r[1]), "=r"(r[2]), "=r"(r[3]) : "r"(addr));
}
__device__ __forceinline__ void mma16816(float* c, const unsigned* a, const unsigned* b) {
    asm volatile("mma.sync.aligned.m16n8k16.row.col.f32.bf16.bf16.f32 "
        "{%0,%1,%2,%3}, {%4,%5,%6,%7}, {%8,%9}, {%0,%1,%2,%3};"
        : "+f"(c[0]), "+f"(c[1]), "+f"(c[2]), "+f"(c[3])
        : "r"(a[0]), "r"(a[1]), "r"(a[2]), "r"(a[3]), "r"(b[0]), "r"(b[1]));
}
// split fp32 pair -> (hi bf16x2, lo bf16x2)
__device__ __forceinline__ uint2 splitpack(float x0, float x1) {
    __nv_bfloat162 h = __float22bfloat162_rn(make_float2(x0, x1));
    float2 hf = __bfloat1622float2(h);
    __nv_bfloat162 l = __float22bfloat162_rn(make_float2(x0 - hf.x, x1 - hf.y));
    uint2 o;
    o.x = *(unsigned*)&h;
    o.y = *(unsigned*)&l;
    return o;
}

// ---------------- mask dtype detection ----------------
__global__ void detect_mask_kernel(const unsigned int* __restrict__ m, int nwords) {
    __shared__ int flags[3];
    if (threadIdx.x < 3) flags[threadIdx.x] = 0;
    __syncthreads();
    for (int i = threadIdx.x; i < nwords; i += blockDim.x) {
        unsigned w = m[i];
        if (w == 0x3F803F80u || w == 0x00003F80u) atomicOr(&flags[0], 1);
        else if (w == 0x3F800000u) atomicOr(&flags[1], 1);
        else if (w > 1u) {
            unsigned b0 = w & 255u, b1 = (w >> 8) & 255u, b2 = (w >> 16) & 255u, b3 = w >> 24;
            if (b0 <= 1u && b1 <= 1u && b2 <= 1u && b3 <= 1u) atomicOr(&flags[2], 1);
        }
    }
    __syncthreads();
    if (threadIdx.x == 0) {
        int kind;
        if (flags[0]) kind = 3;
        else if (flags[1]) kind = 2;
        else if (flags[2]) kind = 0;
        else kind = 1;
        g_mask_kind = kind;
    }
}

__device__ __forceinline__ float mask_val(const void* p, int i) {
    int k = g_mask_kind;
    if (k == 0) return ((const unsigned char*)p)[i] ? 1.f : 0.f;
    if (k == 1) return ((const int*)p)[i] ? 1.f : 0.f;
    if (k == 2) return ((const float*)p)[i];
    return __bfloat162float(((const __nv_bfloat16*)p)[i]);
}

// ---------------- pre-split a 256x256 fp32 matrix into tiled hi/lo bf16 ----------------
// layout: per (nh2 = n-half 0..1, kc = k-chunk 0..3): hi block [128 rows x 72 ushorts pitch]
// (9216 ushorts) then lo block (9216). Block index = nh2*4+kc.
__global__ __launch_bounds__(256) void split_wb(const float* __restrict__ src, int srcBatchStride,
                                                ushortT* __restrict__ dst, int dstBatchStride) {
    int blk = blockIdx.x;            // nh2*4 + kc
    int nh2 = blk >> 2, kc = blk & 3;
    src += (size_t)blockIdx.y * srcBatchStride;
    dst += (size_t)blockIdx.y * dstBatchStride;
    int tid = threadIdx.x;
    size_t ubase = (size_t)blk * 18432;
#pragma unroll
    for (int i = 0; i < 8; i++) {
        int idx = tid + i * 256;
        int r = idx >> 4, c4 = (idx & 15) * 4;
        float4 v = *(const float4*)&src[(size_t)(nh2 * 128 + r) * EE + kc * 64 + c4];
        uint2 s0 = splitpack(v.x, v.y);
        uint2 s1 = splitpack(v.z, v.w);
        ushortT* hp = dst + ubase + r * 72 + c4;
        *(unsigned*)hp = s0.x; *(unsigned*)(hp + 2) = s1.x;
        ushortT* lp = hp + 9216;
        *(unsigned*)lp = s0.y; *(unsigned*)(lp + 2) = s1.y;
    }
}

// ================= mma.sync split-bf16 GEMM: C[M,256] = A[M,256] @ B[256,256]^T =================
#define EPI_PLAIN 0
#define EPI_FEAT  1
#define EPI_VPROJ 2
#define PITCHB 144            // smem row pitch in bytes (72 bf16) -> conflict-free ldmatrix
#define TILEB (128*PITCHB)    // 18432 B per tile array

extern __shared__ char dyn_smem[];

__global__ void __launch_bounds__(256, 2) tgemm(
    const float* __restrict__ A, const ushortT* __restrict__ Bsp,
    const float* __restrict__ bias, float* __restrict__ C,
    int epi, const void* __restrict__ mask, float scale,
    const float* __restrict__ zrow, int bspBatchStride)
{
    char* smAh = dyn_smem;
    char* smAl = dyn_smem + TILEB;
    char* smBh = dyn_smem + 2 * TILEB;   // Bh then Bl contiguous (36864 B)
    uint32_t AhU = smem_u32(smAh), AlU = smem_u32(smAl);
    uint32_t BhU = smem_u32(smBh), BlU = BhU + TILEB;

    int tid = threadIdx.x, wid = tid >> 5, lane = tid & 31;
    int wm = wid >> 2, wn = wid & 3;                  // warp grid 2 x 4
    int bm = blockIdx.y * 128, bn = blockIdx.x * 128;
    if (bspBatchStride) Bsp += (size_t)(bm / LL) * bspBatchStride;

    int lmat = lane >> 3, lrow = lane & 7;
    int a_roff = ((lmat & 1) ? 8 : 0) + lrow;
    int a_coff = (lmat & 2) ? 16 : 0;
    int b_roff = ((lmat & 2) ? 8 : 0) + lrow;
    int b_coff = (lmat & 1) ? 16 : 0;

    float acc[4][4][4];
#pragma unroll
    for (int mi = 0; mi < 4; mi++)
#pragma unroll
        for (int ni = 0; ni < 4; ni++)
#pragma unroll
            for (int j = 0; j < 4; j++) acc[mi][ni][j] = 0.f;

    for (int kc = 0; kc < 4; kc++) {
        __syncthreads();
        // ---- B: async copy of pre-split tile (hi+lo, 36864 B contiguous) ----
        {
            const char* bsrc = (const char*)(Bsp + (size_t)(blockIdx.x * 4 + kc) * 18432);
            uint32_t db = BhU + tid * 144;
            const char* sp = bsrc + tid * 144;
#pragma unroll
            for (int j = 0; j < 9; j++)
                asm volatile("cp.async.cg.shared.global [%0], [%1], 16;"
                    :: "r"(db + j * 16), "l"(sp + j * 16));
            asm volatile("cp.async.commit_group;" ::: "memory");
        }
        // ---- A: load fp32, split into hi/lo bf16 ----
#pragma unroll
        for (int i = 0; i < 8; i++) {
            int idx = tid + i * 256;
            int r = idx >> 4, c4 = (idx & 15) << 2;
            int off = r * PITCHB + c4 * 2;
            float4 av = *(const float4*)&A[(size_t)(bm + r) * EE + kc * 64 + c4];
            if (zrow) {
                float z = zrow[(bm + r) * HH + ((kc * 64 + c4) >> 5)];
                av.x *= z; av.y *= z; av.z *= z; av.w *= z;
            }
            uint2 s0 = splitpack(av.x, av.y);
            uint2 s1 = splitpack(av.z, av.w);
            *(uint2*)(smAh + off) = make_uint2(s0.x, s1.x);
            *(uint2*)(smAl + off) = make_uint2(s0.y, s1.y);
        }
        asm volatile("cp.async.wait_group 0;" ::: "memory");
        __syncthreads();
        // ---- compute: 4 k16-steps, 3 split terms each ----
#pragma unroll
        for (int ks = 0; ks < 4; ks++) {
            int cbb = ks * 32;
            unsigned ah[4][4], bh[4][2], bx[4][2], tmp[4];
#pragma unroll
            for (int mi = 0; mi < 4; mi++) {
                int rb = wm * 64 + mi * 16;
                ldsm4(ah[mi], AhU + (rb + a_roff) * PITCHB + cbb + a_coff);
            }
#pragma unroll
            for (int p = 0; p < 2; p++) {
                int nb = wn * 32 + p * 16;
                ldsm4(tmp, BhU + (nb + b_roff) * PITCHB + cbb + b_coff);
                bh[2*p][0] = tmp[0]; bh[2*p][1] = tmp[1];
                bh[2*p+1][0] = tmp[2]; bh[2*p+1][1] = tmp[3];
            }
#pragma unroll
            for (int mi = 0; mi < 4; mi++)
#pragma unroll
                for (int ni = 0; ni < 4; ni++) mma16816(acc[mi][ni], ah[mi], bh[ni]);
#pragma unroll
            for (int p = 0; p < 2; p++) {
                int nb = wn * 32 + p * 16;
                ldsm4(tmp, BlU + (nb + b_roff) * PITCHB + cbb + b_coff);
                bx[2*p][0] = tmp[0]; bx[2*p][1] = tmp[1];
                bx[2*p+1][0] = tmp[2]; bx[2*p+1][1] = tmp[3];
            }
#pragma unroll
            for (int mi = 0; mi < 4; mi++)
#pragma unroll
                for (int ni = 0; ni < 4; ni++) mma16816(acc[mi][ni], ah[mi], bx[ni]);
#pragma unroll
            for (int mi = 0; mi < 4; mi++) {
                int rb = wm * 64 + mi * 16;
                ldsm4(ah[mi], AlU + (rb + a_roff) * PITCHB + cbb + a_coff);
            }
#pragma unroll
            for (int mi = 0; mi < 4; mi++)
#pragma unroll
                for (int ni = 0; ni < 4; ni++) mma16816(acc[mi][ni], ah[mi], bh[ni]);
        }
    }

    // ---- epilogue ----
    int g = lane >> 2, tc = lane & 3;
#pragma unroll
    for (int mi = 0; mi < 4; mi++) {
        int r0 = bm + wm * 64 + mi * 16 + g;
        int r1 = r0 + 8;
        float mv0 = 1.f, mv1 = 1.f;
        if (epi != EPI_PLAIN) { mv0 = mask_val(mask, r0); mv1 = mask_val(mask, r1); }
#pragma unroll
        for (int ni = 0; ni < 4; ni++) {
            int col = bn + wn * 32 + ni * 8 + tc * 2;
            float c0 = acc[mi][ni][0], c1 = acc[mi][ni][1];
            float c2 = acc[mi][ni][2], c3 = acc[mi][ni][3];
            if (epi == EPI_FEAT) {
                float b0 = bias[col], b1 = bias[col + 1];
                c0 += b0; c1 += b1; c2 += b0; c3 += b1;
                c0 = c0 > 0.f ? c0 + 1.f : expf(c0);
                c1 = c1 > 0.f ? c1 + 1.f : expf(c1);
                c2 = c2 > 0.f ? c2 + 1.f : expf(c2);
                c3 = c3 > 0.f ? c3 + 1.f : expf(c3);
                c0 *= mv0; c1 *= mv0; c2 *= mv1; c3 *= mv1;
            } else if (epi == EPI_VPROJ) {
                float b0 = bias[col], b1 = bias[col + 1];
                c0 = (c0 + b0) * mv0 * scale; c1 = (c1 + b1) * mv0 * scale;
                c2 = (c2 + b0) * mv1 * scale; c3 = (c3 + b1) * mv1 * scale;
            }
            *(float2*)&C[(size_t)r0 * EE + col] = make_float2(c0, c1);
            *(float2*)&C[(size_t)r1 * EE + col] = make_float2(c2, c3);
        }
    }
}

// ---------------- KV aggregation: register-tiled partial sums over S chunks ----------------
__global__ __launch_bounds__(256) void kv_partial() {
    int nh = blockIdx.x;
    int n = nh >> 3, h = nh & 7;
    int chunk = blockIdx.y;
    __shared__ float Ks[64][32];
    __shared__ float Vs[64][32];
    __shared__ float red[4][1056];
    int tid = threadIdx.x;
    int grp = tid >> 6;              // 0..3: s-partition
    int gt = tid & 63;
    int dg = gt >> 3;                // 0..7 -> d0 = dg*4
    int vg = gt & 7;                 // 0..7 -> v0 = vg*4
    float acc[4][4] = {};
    float ks[4] = {};
    int s0base = chunk * CHS;
    const float* Kp = g_Kf + (size_t)n * SS * EE + h * DD;
    const float* Vp = g_Vm + (size_t)n * SS * EE + h * DD;
    for (int s0 = 0; s0 < CHS; s0 += 64) {
#pragma unroll
        for (int r = 0; r < 2; r++) {
            int idx = tid + r * 256;
            int row = idx >> 3, c = (idx & 7) * 4;
            size_t gidx = (size_t)(s0base + s0 + row) * EE + c;
            *(float4*)&Ks[row][c] = *(const float4*)&Kp[gidx];
            *(float4*)&Vs[row][c] = *(const float4*)&Vp[gidx];
        }
        __syncthreads();
#pragma unroll
        for (int si = 0; si < 16; si++) {
            int s = grp * 16 + si;
            float4 kk = *(const float4*)&Ks[s][dg * 4];
            float4 vv = *(const float4*)&Vs[s][vg * 4];
            float ka[4] = {kk.x, kk.y, kk.z, kk.w};
            float va[4] = {vv.x, vv.y, vv.z, vv.w};
#pragma unroll
            for (int i = 0; i < 4; i++) {
                ks[i] += ka[i];
#pragma unroll
                for (int j = 0; j < 4; j++) acc[i][j] += ka[i] * va[j];
            }
        }
        __syncthreads();
    }
    // write partials to smem, reduce the 4 s-partitions
#pragma unroll
    for (int i = 0; i < 4; i++)
#pragma unroll
        for (int j = 0; j < 4; j++)
            red[grp][(dg * 4 + i) * 32 + vg * 4 + j] = acc[i][j];
    if (vg == 0) {
#pragma unroll
        for (int i = 0; i < 4; i++) red[grp][1024 + dg * 4 + i] = ks[i];
    }
    __syncthreads();
    float* P = g_part + ((size_t)chunk * 64 + nh) * 1056;
    for (int i = tid; i < 1056; i += 256)
        P[i] = red[0][i] + red[1][i] + red[2][i] + red[3][i];
}

__global__ void kv_reduce() {
    int nh = blockIdx.x;
    for (int i = threadIdx.x; i < 1056; i += blockDim.x) {
        float s = 0;
        for (int c = 0; c < NCHUNK; c++) s += g_part[((size_t)c * 64 + nh) * 1056 + i];
        g_KV[(size_t)nh * 1056 + i] = s;
    }
}

__global__ __launch_bounds__(256) void make_ut(const float* __restrict__ Wm) {
    int nh = blockIdx.x; int n = nh >> 3, h = nh & 7;
    __shared__ float KVs[32][32];
    int tid = threadIdx.x;
    for (int i = tid; i < 1024; i += 256) KVs[i >> 5][i & 31] = g_KV[(size_t)nh * 1056 + i];
    __syncthreads();
    int ep = tid;
    float w[32];
#pragma unroll
    for (int v = 0; v < 32; v++) w[v] = Wm[(size_t)ep * EE + h * DD + v];
    float* out = g_UT + ((size_t)n * EE + ep) * EE + h * DD;
#pragma unroll
    for (int d2 = 0; d2 < 32; d2++) {
        float a = 0;
#pragma unroll
        for (int v = 0; v < 32; v++) a += KVs[d2][v] * w[v];
        out[d2] = a * (float)SS;
    }
}

__global__ void z_kernel() {
    int t = blockIdx.x * blockDim.x + threadIdx.x;
    int row = t >> 3, h = t & 7;
    int n = row / LL;
    const float* q = g_Qf + (size_t)row * EE + h * DD;
    const float* ks = g_KV + (size_t)(n * HH + h) * 1056 + 1024;
    float a = 0;
#pragma unroll
    for (int d2 = 0; d2 < 32; d2++) a += q[d2] * ks[d2];
    g_Z[t] = 1.f / (a + EPSV);
}

// ---------------- launch ----------------
extern "C" void kernel_launch(void* const* d_in, const int* in_sizes, int n_in,
                              void* d_out, int out_size) {
    const float* q  = (const float*)d_in[0];
    const float* k  = (const float*)d_in[1];
    const float* v  = (const float*)d_in[2];
    const void*  qm = d_in[3];
    const void*  km = d_in[4];
    const float* Wq = (const float*)d_in[5];
    const float* bq = (const float*)d_in[6];
    const float* Wk = (const float*)d_in[7];
    const float* bk = (const float*)d_in[8];
    const float* Wv = (const float*)d_in[9];
    const float* bv = (const float*)d_in[10];
    const float* Wm = (const float*)d_in[11];
    float* out = (float*)d_out;

    float *Qf, *Kf, *Vm, *UT, *Z;
    ushortT *Wsp, *UTsp;
    cudaGetSymbolAddress((void**)&Qf, g_Qf);
    cudaGetSymbolAddress((void**)&Kf, g_Kf);
    cudaGetSymbolAddress((void**)&Vm, g_Vm);
    cudaGetSymbolAddress((void**)&UT, g_UT);
    cudaGetSymbolAddress((void**)&Z,  g_Z);
    cudaGetSymbolAddress((void**)&Wsp, g_Wsp);
    cudaGetSymbolAddress((void**)&UTsp, g_UTsp);

    const int SMEM_SZ = 4 * TILEB;  // 73728 B
    cudaFuncSetAttribute(tgemm, cudaFuncAttributeMaxDynamicSharedMemorySize, SMEM_SZ);

    detect_mask_kernel<<<1, 256>>>((const unsigned int*)km, 2048);
    split_wb<<<dim3(8, 1), 256>>>(Wq, 0, Wsp, 0);
    split_wb<<<dim3(8, 1), 256>>>(Wk, 0, Wsp + MATU, 0);
    split_wb<<<dim3(8, 1), 256>>>(Wv, 0, Wsp + 2 * MATU, 0);

    dim3 gr(2, NTOK / 128);  // (2, 256)
    tgemm<<<gr, 256, SMEM_SZ>>>(q, Wsp,            bq, Qf, EPI_FEAT,  qm, 1.f, nullptr, 0);
    tgemm<<<gr, 256, SMEM_SZ>>>(k, Wsp + MATU,     bk, Kf, EPI_FEAT,  km, 1.f, nullptr, 0);
    tgemm<<<gr, 256, SMEM_SZ>>>(v, Wsp + 2 * MATU, bv, Vm, EPI_VPROJ, km, 1.f / (float)SS, nullptr, 0);

    kv_partial<<<dim3(64, NCHUNK), 256>>>();
    kv_reduce<<<64, 256>>>();
    make_ut<<<64, 256>>>(Wm);
    split_wb<<<dim3(8, Nb), 256>>>(UT, EE * EE, UTsp, MATU);
    z_kernel<<<(NTOK * HH) / 256, 256>>>();

    tgemm<<<gr, 256, SMEM_SZ>>>(Qf, UTsp, nullptr, out, EPI_PLAIN, nullptr, 1.f, Z, MATU);
}

// round 7
// speedup vs baseline: 1.1226x; 1.1226x over previous
#include <cuda_runtime.h>
#include <cuda_bf16.h>
#include <cstdint>

#define Nb 8
#define LL 4096
#define SS 4096
#define EE 256
#define HH 8
#define DD 32
#define NTOK (Nb*LL)
#define EPSV 1e-6f
#define NCHUNK 8
#define CHS (SS/NCHUNK)

typedef unsigned short ushortT;

// ---------------- scratch ----------------
__device__ float g_Qf[NTOK*EE];
__device__ float g_Kf[Nb*SS*EE];
__device__ float g_Vm[Nb*SS*EE];
__device__ float g_part[NCHUNK*Nb*HH*1056];
__device__ float g_KV[Nb*HH*1056];
__device__ float g_Z[NTOK*HH];
__device__ int   g_mask_kind;
#define MATU 147456                    // ushorts per 256x256 split matrix
__device__ ushortT g_Wsp[3*MATU];      // Wq, Wk, Wv  (tiled hi/lo bf16)
__device__ ushortT g_UTsp[Nb*MATU];    // per-batch UT (tiled hi/lo bf16)

// ---------------- helpers ----------------
__device__ __forceinline__ uint32_t smem_u32(const void* p) {
    uint32_t a;
    asm("{ .reg .u64 t; cvta.to.shared.u64 t, %1; cvt.u32.u64 %0, t; }" : "=r"(a) : "l"(p));
    return a;
}
__device__ __forceinline__ void ldsm4(unsigned* r, uint32_t addr) {
    asm volatile("ldmatrix.sync.aligned.m8n8.x4.shared.b16 {%0,%1,%2,%3}, [%4];"
        : "=r"(r[0]), "=r"(r[1]), "=r"(r[2]), "=r"(r[3]) : "r"(addr));
}
__device__ __forceinline__ void mma16816(float* c, const unsigned* a, const unsigned* b) {
    asm volatile("mma.sync.aligned.m16n8k16.row.col.f32.bf16.bf16.f32 "
        "{%0,%1,%2,%3}, {%4,%5,%6,%7}, {%8,%9}, {%0,%1,%2,%3};"
        : "+f"(c[0]), "+f"(c[1]), "+f"(c[2]), "+f"(c[3])
        : "r"(a[0]), "r"(a[1]), "r"(a[2]), "r"(a[3]), "r"(b[0]), "r"(b[1]));
}
__device__ __forceinline__ uint2 splitpack(float x0, float x1) {
    __nv_bfloat162 h = __float22bfloat162_rn(make_float2(x0, x1));
    float2 hf = __bfloat1622float2(h);
    __nv_bfloat162 l = __float22bfloat162_rn(make_float2(x0 - hf.x, x1 - hf.y));
    uint2 o;
    o.x = *(unsigned*)&h;
    o.y = *(unsigned*)&l;
    return o;
}

// ---------------- mask dtype detection ----------------
__global__ void detect_mask_kernel(const unsigned int* __restrict__ m, int nwords) {
    __shared__ int flags[3];
    if (threadIdx.x < 3) flags[threadIdx.x] = 0;
    __syncthreads();
    for (int i = threadIdx.x; i < nwords; i += blockDim.x) {
        unsigned w = m[i];
        if (w == 0x3F803F80u || w == 0x00003F80u) atomicOr(&flags[0], 1);
        else if (w == 0x3F800000u) atomicOr(&flags[1], 1);
        else if (w > 1u) {
            unsigned b0 = w & 255u, b1 = (w >> 8) & 255u, b2 = (w >> 16) & 255u, b3 = w >> 24;
            if (b0 <= 1u && b1 <= 1u && b2 <= 1u && b3 <= 1u) atomicOr(&flags[2], 1);
        }
    }
    __syncthreads();
    if (threadIdx.x == 0) {
        int kind;
        if (flags[0]) kind = 3;
        else if (flags[1]) kind = 2;
        else if (flags[2]) kind = 0;
        else kind = 1;
        g_mask_kind = kind;
    }
}

__device__ __forceinline__ float mask_val(const void* p, int i) {
    int k = g_mask_kind;
    if (k == 0) return ((const unsigned char*)p)[i] ? 1.f : 0.f;
    if (k == 1) return ((const int*)p)[i] ? 1.f : 0.f;
    if (k == 2) return ((const float*)p)[i];
    return __bfloat162float(((const __nv_bfloat16*)p)[i]);
}

// ---------------- pre-split the 3 weight matrices (one launch) ----------------
// split layout per 256x256 matrix: block(nh2 0..1, kc 0..3) = 18432 ushorts:
//   hi[128 rows x 72 pitch] (9216) then lo (9216)
__global__ __launch_bounds__(256) void split_w3(const float* __restrict__ W0,
                                                const float* __restrict__ W1,
                                                const float* __restrict__ W2) {
    int y = blockIdx.y;
    const float* src = y == 0 ? W0 : (y == 1 ? W1 : W2);
    ushortT* dst = g_Wsp + (size_t)y * MATU;
    int blk = blockIdx.x;            // nh2*4 + kc
    int nh2 = blk >> 2, kc = blk & 3;
    int tid = threadIdx.x;
    size_t ubase = (size_t)blk * 18432;
#pragma unroll
    for (int i = 0; i < 8; i++) {
        int idx = tid + i * 256;
        int r = idx >> 4, c4 = (idx & 15) * 4;
        float4 v = *(const float4*)&src[(size_t)(nh2 * 128 + r) * EE + kc * 64 + c4];
        uint2 s0 = splitpack(v.x, v.y);
        uint2 s1 = splitpack(v.z, v.w);
        ushortT* hp = dst + ubase + r * 72 + c4;
        *(unsigned*)hp = s0.x; *(unsigned*)(hp + 2) = s1.x;
        ushortT* lp = hp + 9216;
        *(unsigned*)lp = s0.y; *(unsigned*)(lp + 2) = s1.y;
    }
}

// ================= pipelined mma.sync split-bf16 GEMM =================
#define EPI_PLAIN 0
#define EPI_FEAT  1
#define EPI_VPROJ 2
#define PITCHB 144
#define TILEB (128*PITCHB)    // 18432 B (one hi or lo half)
#define BSTAGE (2*TILEB)      // 36864 B per B stage (hi|lo)
#define SMEM_SZ (2*TILEB + 2*BSTAGE)   // A(hi|lo) + 2 B stages = 110592 B

extern __shared__ char dyn_smem[];

__global__ void __launch_bounds__(512, 2) tgemm(
    const float* __restrict__ A0, const float* __restrict__ A1, const float* __restrict__ A2,
    const ushortT* __restrict__ Bsp, int bStrideZ,
    const float* __restrict__ bias0, const float* __restrict__ bias1, const float* __restrict__ bias2,
    float* __restrict__ C0, float* __restrict__ C1, float* __restrict__ C2,
    int epi0, int epi1, int epi2,
    const void* __restrict__ mask0, const void* __restrict__ mask1, const void* __restrict__ mask2,
    float scale, const float* __restrict__ zrow, int bBatchStride)
{
    int z = blockIdx.z;
    const float* A   = z == 0 ? A0 : (z == 1 ? A1 : A2);
    const float* bias = z == 0 ? bias0 : (z == 1 ? bias1 : bias2);
    float* C         = z == 0 ? C0 : (z == 1 ? C1 : C2);
    int epi          = z == 0 ? epi0 : (z == 1 ? epi1 : epi2);
    const void* mask = z == 0 ? mask0 : (z == 1 ? mask1 : mask2);

    uint32_t AhU = smem_u32(dyn_smem);
    uint32_t AlU = AhU + TILEB;
    uint32_t BsU = AhU + 2 * TILEB;

    int tid = threadIdx.x, wid = tid >> 5, lane = tid & 31;
    int wm = wid >> 2, wn = wid & 3;                  // warp grid 4 x 4
    int bm = blockIdx.y * 128, bn = blockIdx.x * 128;
    const ushortT* B = Bsp + (size_t)z * bStrideZ;
    if (bBatchStride) B += (size_t)(bm / LL) * bBatchStride;

    int lmat = lane >> 3, lrow = lane & 7;
    int a_roff = ((lmat & 1) ? 8 : 0) + lrow;
    int a_coff = (lmat & 2) ? 16 : 0;
    int b_roff = ((lmat & 2) ? 8 : 0) + lrow;
    int b_coff = (lmat & 1) ? 16 : 0;

    float acc[2][4][4];
#pragma unroll
    for (int mi = 0; mi < 2; mi++)
#pragma unroll
        for (int ni = 0; ni < 4; ni++)
#pragma unroll
            for (int j = 0; j < 4; j++) acc[mi][ni][j] = 0.f;

    float4 pf[4];

    // --- helpers as macros ---
#define ISSUE_B(kc, stage) do { \
        const char* _src = (const char*)(B + (size_t)(blockIdx.x * 4 + (kc)) * 18432); \
        uint32_t _db = BsU + (stage) * BSTAGE; \
        _Pragma("unroll") \
        for (int _j = 0; _j < 5; _j++) { \
            int _id = tid + _j * 512; \
            if (_id < 2304) \
                asm volatile("cp.async.cg.shared.global [%0], [%1], 16;" \
                    :: "r"(_db + _id * 16), "l"(_src + _id * 16)); \
        } \
        asm volatile("cp.async.commit_group;" ::: "memory"); \
    } while (0)

#define LOAD_A(kc) do { \
        _Pragma("unroll") \
        for (int _i = 0; _i < 4; _i++) { \
            int _idx = tid + _i * 512; \
            int _r = _idx >> 4, _c4 = (_idx & 15) << 2; \
            pf[_i] = *(const float4*)&A[(size_t)(bm + _r) * EE + (kc) * 64 + _c4]; \
            if (zrow) { \
                float _z = zrow[(bm + _r) * HH + (((kc) * 64 + _c4) >> 5)]; \
                pf[_i].x *= _z; pf[_i].y *= _z; pf[_i].z *= _z; pf[_i].w *= _z; \
            } \
        } \
    } while (0)

#define STORE_A() do { \
        _Pragma("unroll") \
        for (int _i = 0; _i < 4; _i++) { \
            int _idx = tid + _i * 512; \
            int _r = _idx >> 4, _c4 = (_idx & 15) << 2; \
            uint32_t _off = _r * PITCHB + _c4 * 2; \
            uint2 _s0 = splitpack(pf[_i].x, pf[_i].y); \
            uint2 _s1 = splitpack(pf[_i].z, pf[_i].w); \
            asm volatile("st.shared.v2.b32 [%0], {%1,%2};" :: "r"(AhU + _off), "r"(_s0.x), "r"(_s1.x) : "memory"); \
            asm volatile("st.shared.v2.b32 [%0], {%1,%2};" :: "r"(AlU + _off), "r"(_s0.y), "r"(_s1.y) : "memory"); \
        } \
    } while (0)

    // --- prologue: B0 + A0 ---
    ISSUE_B(0, 0);
    LOAD_A(0);
    STORE_A();
    asm volatile("cp.async.wait_group 0;" ::: "memory");
    __syncthreads();

    for (int kc = 0; kc < 4; kc++) {
        int s = kc & 1;
        if (kc < 3) {
            ISSUE_B(kc + 1, s ^ 1);
            LOAD_A(kc + 1);
        }
        uint32_t BhU = BsU + s * BSTAGE;
        uint32_t BlU = BhU + TILEB;
        // ---- compute: 4 k16-steps, 3 split terms ----
#pragma unroll
        for (int ks = 0; ks < 4; ks++) {
            int cbb = ks * 32;
            unsigned ah[2][4], bh[4][2], bx[4][2], tmp[4];
#pragma unroll
            for (int mi = 0; mi < 2; mi++) {
                int rb = wm * 32 + mi * 16;
                ldsm4(ah[mi], AhU + (rb + a_roff) * PITCHB + cbb + a_coff);
            }
#pragma unroll
            for (int p = 0; p < 2; p++) {
                int nb = wn * 32 + p * 16;
                ldsm4(tmp, BhU + (nb + b_roff) * PITCHB + cbb + b_coff);
                bh[2*p][0] = tmp[0]; bh[2*p][1] = tmp[1];
                bh[2*p+1][0] = tmp[2]; bh[2*p+1][1] = tmp[3];
            }
#pragma unroll
            for (int mi = 0; mi < 2; mi++)
#pragma unroll
                for (int ni = 0; ni < 4; ni++) mma16816(acc[mi][ni], ah[mi], bh[ni]);
#pragma unroll
            for (int p = 0; p < 2; p++) {
                int nb = wn * 32 + p * 16;
                ldsm4(tmp, BlU + (nb + b_roff) * PITCHB + cbb + b_coff);
                bx[2*p][0] = tmp[0]; bx[2*p][1] = tmp[1];
                bx[2*p+1][0] = tmp[2]; bx[2*p+1][1] = tmp[3];
            }
#pragma unroll
            for (int mi = 0; mi < 2; mi++)
#pragma unroll
                for (int ni = 0; ni < 4; ni++) mma16816(acc[mi][ni], ah[mi], bx[ni]);
#pragma unroll
            for (int mi = 0; mi < 2; mi++) {
                int rb = wm * 32 + mi * 16;
                ldsm4(ah[mi], AlU + (rb + a_roff) * PITCHB + cbb + a_coff);
            }
#pragma unroll
            for (int mi = 0; mi < 2; mi++)
#pragma unroll
                for (int ni = 0; ni < 4; ni++) mma16816(acc[mi][ni], ah[mi], bh[ni]);
        }
        __syncthreads();                // A smem free
        if (kc < 3) {
            STORE_A();                  // A[kc+1] into smem
            asm volatile("cp.async.wait_group 0;" ::: "memory");
            __syncthreads();
        }
    }

    // ---- epilogue ----
    int g = lane >> 2, tc = lane & 3;
#pragma unroll
    for (int mi = 0; mi < 2; mi++) {
        int r0 = bm + wm * 32 + mi * 16 + g;
        int r1 = r0 + 8;
        float mv0 = 1.f, mv1 = 1.f;
        if (epi != EPI_PLAIN) { mv0 = mask_val(mask, r0); mv1 = mask_val(mask, r1); }
#pragma unroll
        for (int ni = 0; ni < 4; ni++) {
            int col = bn + wn * 32 + ni * 8 + tc * 2;
            float c0 = acc[mi][ni][0], c1 = acc[mi][ni][1];
            float c2 = acc[mi][ni][2], c3 = acc[mi][ni][3];
            if (epi == EPI_FEAT) {
                float b0 = bias[col], b1 = bias[col + 1];
                c0 += b0; c1 += b1; c2 += b0; c3 += b1;
                c0 = c0 > 0.f ? c0 + 1.f : expf(c0);
                c1 = c1 > 0.f ? c1 + 1.f : expf(c1);
                c2 = c2 > 0.f ? c2 + 1.f : expf(c2);
                c3 = c3 > 0.f ? c3 + 1.f : expf(c3);
                c0 *= mv0; c1 *= mv0; c2 *= mv1; c3 *= mv1;
            } else if (epi == EPI_VPROJ) {
                float b0 = bias[col], b1 = bias[col + 1];
                c0 = (c0 + b0) * mv0 * scale; c1 = (c1 + b1) * mv0 * scale;
                c2 = (c2 + b0) * mv1 * scale; c3 = (c3 + b1) * mv1 * scale;
            }
            *(float2*)&C[(size_t)r0 * EE + col] = make_float2(c0, c1);
            *(float2*)&C[(size_t)r1 * EE + col] = make_float2(c2, c3);
        }
    }
#undef ISSUE_B
#undef LOAD_A
#undef STORE_A
}

// ---------------- KV aggregation: register-tiled partial sums ----------------
__global__ __launch_bounds__(256) void kv_partial() {
    int nh = blockIdx.x;
    int n = nh >> 3, h = nh & 7;
    int chunk = blockIdx.y;
    __shared__ float Ks[64][32];
    __shared__ float Vs[64][32];
    __shared__ float red[4][1056];
    int tid = threadIdx.x;
    int grp = tid >> 6;
    int gt = tid & 63;
    int dg = gt >> 3;
    int vg = gt & 7;
    float acc[4][4] = {};
    float ks[4] = {};
    int s0base = chunk * CHS;
    const float* Kp = g_Kf + (size_t)n * SS * EE + h * DD;
    const float* Vp = g_Vm + (size_t)n * SS * EE + h * DD;
    for (int s0 = 0; s0 < CHS; s0 += 64) {
#pragma unroll
        for (int r = 0; r < 2; r++) {
            int idx = tid + r * 256;
            int row = idx >> 3, c = (idx & 7) * 4;
            size_t gidx = (size_t)(s0base + s0 + row) * EE + c;
            *(float4*)&Ks[row][c] = *(const float4*)&Kp[gidx];
            *(float4*)&Vs[row][c] = *(const float4*)&Vp[gidx];
        }
        __syncthreads();
#pragma unroll
        for (int si = 0; si < 16; si++) {
            int s = grp * 16 + si;
            float4 kk = *(const float4*)&Ks[s][dg * 4];
            float4 vv = *(const float4*)&Vs[s][vg * 4];
            float ka[4] = {kk.x, kk.y, kk.z, kk.w};
            float va[4] = {vv.x, vv.y, vv.z, vv.w};
#pragma unroll
            for (int i = 0; i < 4; i++) {
                ks[i] += ka[i];
#pragma unroll
                for (int j = 0; j < 4; j++) acc[i][j] += ka[i] * va[j];
            }
        }
        __syncthreads();
    }
#pragma unroll
    for (int i = 0; i < 4; i++)
#pragma unroll
        for (int j = 0; j < 4; j++)
            red[grp][(dg * 4 + i) * 32 + vg * 4 + j] = acc[i][j];
    if (vg == 0) {
#pragma unroll
        for (int i = 0; i < 4; i++) red[grp][1024 + dg * 4 + i] = ks[i];
    }
    __syncthreads();
    float* P = g_part + ((size_t)chunk * 64 + nh) * 1056;
    for (int i = tid; i < 1056; i += 256)
        P[i] = red[0][i] + red[1][i] + red[2][i] + red[3][i];
}

__global__ void kv_reduce() {
    int nh = blockIdx.x;
    for (int i = threadIdx.x; i < 1056; i += blockDim.x) {
        float s = 0;
        for (int c = 0; c < NCHUNK; c++) s += g_part[((size_t)c * 64 + nh) * 1056 + i];
        g_KV[(size_t)nh * 1056 + i] = s;
    }
}

// ---------------- make UT directly in split-bf16 tiled layout ----------------
__global__ __launch_bounds__(256) void make_ut(const float* __restrict__ Wm) {
    int nh = blockIdx.x; int n = nh >> 3, h = nh & 7;
    __shared__ float KVs[32][32];
    int tid = threadIdx.x;
    for (int i = tid; i < 1024; i += 256) KVs[i >> 5][i & 31] = g_KV[(size_t)nh * 1056 + i];
    __syncthreads();
    int ep = tid;
    float w[32];
#pragma unroll
    for (int v = 0; v < 32; v++) w[v] = Wm[(size_t)ep * EE + h * DD + v];
    // dst: batch n, split-block ((ep>>7)*4 + (h>>1)), row ep&127, col (h&1)*32 + d2
    ushortT* dsth = g_UTsp + (size_t)n * MATU
                  + ((size_t)((ep >> 7) * 4 + (h >> 1))) * 18432
                  + (ep & 127) * 72 + (h & 1) * 32;
#pragma unroll
    for (int d2 = 0; d2 < 32; d2++) {
        float a = 0;
#pragma unroll
        for (int v = 0; v < 32; v++) a += KVs[d2][v] * w[v];
        a *= (float)SS;
        __nv_bfloat16 hb = __float2bfloat16(a);
        float hr = __bfloat162float(hb);
        __nv_bfloat16 lb = __float2bfloat16(a - hr);
        dsth[d2] = __bfloat16_as_ushort(hb);
        dsth[9216 + d2] = __bfloat16_as_ushort(lb);
    }
}

__global__ void z_kernel() {
    int t = blockIdx.x * blockDim.x + threadIdx.x;
    int row = t >> 3, h = t & 7;
    int n = row / LL;
    const float* q = g_Qf + (size_t)row * EE + h * DD;
    const float* ks = g_KV + (size_t)(n * HH + h) * 1056 + 1024;
    float a = 0;
#pragma unroll
    for (int d2 = 0; d2 < 32; d2++) a += q[d2] * ks[d2];
    g_Z[t] = 1.f / (a + EPSV);
}

// ---------------- launch ----------------
extern "C" void kernel_launch(void* const* d_in, const int* in_sizes, int n_in,
                              void* d_out, int out_size) {
    const float* q  = (const float*)d_in[0];
    const float* k  = (const float*)d_in[1];
    const float* v  = (const float*)d_in[2];
    const void*  qm = d_in[3];
    const void*  km = d_in[4];
    const float* Wq = (const float*)d_in[5];
    const float* bq = (const float*)d_in[6];
    const float* Wk = (const float*)d_in[7];
    const float* bk = (const float*)d_in[8];
    const float* Wv = (const float*)d_in[9];
    const float* bv = (const float*)d_in[10];
    const float* Wm = (const float*)d_in[11];
    float* out = (float*)d_out;

    float *Qf, *Kf, *Vm, *Z;
    ushortT *Wsp, *UTsp;
    cudaGetSymbolAddress((void**)&Qf, g_Qf);
    cudaGetSymbolAddress((void**)&Kf, g_Kf);
    cudaGetSymbolAddress((void**)&Vm, g_Vm);
    cudaGetSymbolAddress((void**)&Z,  g_Z);
    cudaGetSymbolAddress((void**)&Wsp, g_Wsp);
    cudaGetSymbolAddress((void**)&UTsp, g_UTsp);

    cudaFuncSetAttribute(tgemm, cudaFuncAttributeMaxDynamicSharedMemorySize, SMEM_SZ);

    detect_mask_kernel<<<1, 256>>>((const unsigned int*)km, 2048);
    split_w3<<<dim3(8, 3), 256>>>(Wq, Wk, Wv);

    // fused Q/K/V projections (gridDim.z = 3)
    tgemm<<<dim3(2, NTOK / 128, 3), 512, SMEM_SZ>>>(
        q, k, v, Wsp, MATU,
        bq, bk, bv, Qf, Kf, Vm,
        EPI_FEAT, EPI_FEAT, EPI_VPROJ,
        qm, km, km,
        1.f / (float)SS, nullptr, 0);

    kv_partial<<<dim3(64, NCHUNK), 256>>>();
    kv_reduce<<<64, 256>>>();
    make_ut<<<64, 256>>>(Wm);
    z_kernel<<<(NTOK * HH) / 256, 256>>>();

    // final: (Qf * Z) @ UT[n]^T
    tgemm<<<dim3(2, NTOK / 128, 1), 512, SMEM_SZ>>>(
        Qf, Qf, Qf, UTsp, 0,
        nullptr, nullptr, nullptr, out, out, out,
        EPI_PLAIN, EPI_PLAIN, EPI_PLAIN,
        nullptr, nullptr, nullptr,
        1.f, Z, MATU);
}

// round 8
// speedup vs baseline: 1.2818x; 1.1419x over previous
#include <cuda_runtime.h>
#include <cuda_bf16.h>
#include <cstdint>

#define Nb 8
#define LL 4096
#define SS 4096
#define EE 256
#define HH 8
#define DD 32
#define NTOK (Nb*LL)
#define EPSV 1e-6f
#define NCHUNK 8
#define CHS (SS/NCHUNK)

typedef unsigned short ushortT;

// ---------------- scratch ----------------
__device__ float g_Kf[Nb*SS*EE];
__device__ float g_Vm[Nb*SS*EE];
__device__ float g_part[NCHUNK*Nb*HH*1056];
__device__ float g_KV[Nb*HH*1056];
__device__ int   g_mask_kind;
#define MATU 147456                    // ushorts per 256x256 split matrix
__device__ ushortT g_Wsp[3*MATU];      // Wq, Wk, Wv  (tiled hi/lo bf16)
__device__ ushortT g_UTsp[Nb*MATU];    // per-batch UT (tiled hi/lo bf16)
// Qf*Z, split-tiled: 256 row-blocks x (4 kc x (hi 9216 | lo 9216)) ushorts
__device__ ushortT g_Qsp[(NTOK/128)*73728];

// ---------------- helpers ----------------
__device__ __forceinline__ uint32_t smem_u32(const void* p) {
    uint32_t a;
    asm("{ .reg .u64 t; cvta.to.shared.u64 t, %1; cvt.u32.u64 %0, t; }" : "=r"(a) : "l"(p));
    return a;
}
__device__ __forceinline__ void ldsm4(unsigned* r, uint32_t addr) {
    asm volatile("ldmatrix.sync.aligned.m8n8.x4.shared.b16 {%0,%1,%2,%3}, [%4];"
        : "=r"(r[0]), "=r"(r[1]), "=r"(r[2]), "=r"(r[3]) : "r"(addr));
}
__device__ __forceinline__ void mma16816(float* c, const unsigned* a, const unsigned* b) {
    asm volatile("mma.sync.aligned.m16n8k16.row.col.f32.bf16.bf16.f32 "
        "{%0,%1,%2,%3}, {%4,%5,%6,%7}, {%8,%9}, {%0,%1,%2,%3};"
        : "+f"(c[0]), "+f"(c[1]), "+f"(c[2]), "+f"(c[3])
        : "r"(a[0]), "r"(a[1]), "r"(a[2]), "r"(a[3]), "r"(b[0]), "r"(b[1]));
}
__device__ __forceinline__ uint2 splitpack(float x0, float x1) {
    __nv_bfloat162 h = __float22bfloat162_rn(make_float2(x0, x1));
    float2 hf = __bfloat1622float2(h);
    __nv_bfloat162 l = __float22bfloat162_rn(make_float2(x0 - hf.x, x1 - hf.y));
    uint2 o;
    o.x = *(unsigned*)&h;
    o.y = *(unsigned*)&l;
    return o;
}

// ---------------- mask dtype detection ----------------
__global__ void detect_mask_kernel(const unsigned int* __restrict__ m, int nwords) {
    __shared__ int flags[3];
    if (threadIdx.x < 3) flags[threadIdx.x] = 0;
    __syncthreads();
    for (int i = threadIdx.x; i < nwords; i += blockDim.x) {
        unsigned w = m[i];
        if (w == 0x3F803F80u || w == 0x00003F80u) atomicOr(&flags[0], 1);
        else if (w == 0x3F800000u) atomicOr(&flags[1], 1);
        else if (w > 1u) {
            unsigned b0 = w & 255u, b1 = (w >> 8) & 255u, b2 = (w >> 16) & 255u, b3 = w >> 24;
            if (b0 <= 1u && b1 <= 1u && b2 <= 1u && b3 <= 1u) atomicOr(&flags[2], 1);
        }
    }
    __syncthreads();
    if (threadIdx.x == 0) {
        int kind;
        if (flags[0]) kind = 3;
        else if (flags[1]) kind = 2;
        else if (flags[2]) kind = 0;
        else kind = 1;
        g_mask_kind = kind;
    }
}

__device__ __forceinline__ float mask_val(const void* p, int i) {
    int k = g_mask_kind;
    if (k == 0) return ((const unsigned char*)p)[i] ? 1.f : 0.f;
    if (k == 1) return ((const int*)p)[i] ? 1.f : 0.f;
    if (k == 2) return ((const float*)p)[i];
    return __bfloat162float(((const __nv_bfloat16*)p)[i]);
}

// ---------------- pre-split the 3 weight matrices ----------------
__global__ __launch_bounds__(256) void split_w3(const float* __restrict__ W0,
                                                const float* __restrict__ W1,
                                                const float* __restrict__ W2) {
    int y = blockIdx.y;
    const float* src = y == 0 ? W0 : (y == 1 ? W1 : W2);
    ushortT* dst = g_Wsp + (size_t)y * MATU;
    int blk = blockIdx.x;
    int nh2 = blk >> 2, kc = blk & 3;
    int tid = threadIdx.x;
    size_t ubase = (size_t)blk * 18432;
#pragma unroll
    for (int i = 0; i < 8; i++) {
        int idx = tid + i * 256;
        int r = idx >> 4, c4 = (idx & 15) * 4;
        float4 v = *(const float4*)&src[(size_t)(nh2 * 128 + r) * EE + kc * 64 + c4];
        uint2 s0 = splitpack(v.x, v.y);
        uint2 s1 = splitpack(v.z, v.w);
        ushortT* hp = dst + ubase + r * 72 + c4;
        *(unsigned*)hp = s0.x; *(unsigned*)(hp + 2) = s1.x;
        ushortT* lp = hp + 9216;
        *(unsigned*)lp = s0.y; *(unsigned*)(lp + 2) = s1.y;
    }
}

// ================= pipelined mma.sync split-bf16 GEMM (projections) =================
#define EPI_FEAT  1   // elu+1, mask -> fp32 C
#define EPI_VPROJ 2   // (x+b)*mask*scale -> fp32 C
#define EPI_QZ    3   // elu+1, mask, fold Z, write split-tiled g_Qsp
#define PITCHB 144
#define TILEB (128*PITCHB)    // 18432 B
#define BSTAGE (2*TILEB)
#define SMEM_SZ (2*TILEB + 2*BSTAGE)   // 110592 B

extern __shared__ char dyn_smem[];

__global__ void __launch_bounds__(512, 2) tgemm(
    const float* __restrict__ A0, const float* __restrict__ A1,
    const ushortT* __restrict__ Bsp, int bStrideZ,
    const float* __restrict__ bias0, const float* __restrict__ bias1,
    float* __restrict__ C0, float* __restrict__ C1,
    int epi0, int epi1,
    const void* __restrict__ mask, float scale)
{
    int z = blockIdx.z;
    const float* A    = z == 0 ? A0 : A1;
    const float* bias = z == 0 ? bias0 : bias1;
    float* C          = z == 0 ? C0 : C1;
    int epi           = z == 0 ? epi0 : epi1;

    uint32_t AhU = smem_u32(dyn_smem);
    uint32_t AlU = AhU + TILEB;
    uint32_t BsU = AhU + 2 * TILEB;

    int tid = threadIdx.x, wid = tid >> 5, lane = tid & 31;
    int wm = wid >> 2, wn = wid & 3;
    int bm = blockIdx.y * 128, bn = blockIdx.x * 128;
    const ushortT* B = Bsp + (size_t)z * bStrideZ;

    int lmat = lane >> 3, lrow = lane & 7;
    int a_roff = ((lmat & 1) ? 8 : 0) + lrow;
    int a_coff = (lmat & 2) ? 16 : 0;
    int b_roff = ((lmat & 2) ? 8 : 0) + lrow;
    int b_coff = (lmat & 1) ? 16 : 0;

    float acc[2][4][4];
#pragma unroll
    for (int mi = 0; mi < 2; mi++)
#pragma unroll
        for (int ni = 0; ni < 4; ni++)
#pragma unroll
            for (int j = 0; j < 4; j++) acc[mi][ni][j] = 0.f;

    float4 pf[4];

#define ISSUE_B(kc, stage) do { \
        const char* _src = (const char*)(B + (size_t)(blockIdx.x * 4 + (kc)) * 18432); \
        uint32_t _db = BsU + (stage) * BSTAGE; \
        _Pragma("unroll") \
        for (int _j = 0; _j < 5; _j++) { \
            int _id = tid + _j * 512; \
            if (_id < 2304) \
                asm volatile("cp.async.cg.shared.global [%0], [%1], 16;" \
                    :: "r"(_db + _id * 16), "l"(_src + _id * 16)); \
        } \
        asm volatile("cp.async.commit_group;" ::: "memory"); \
    } while (0)

#define LOAD_A(kc) do { \
        _Pragma("unroll") \
        for (int _i = 0; _i < 4; _i++) { \
            int _idx = tid + _i * 512; \
            int _r = _idx >> 4, _c4 = (_idx & 15) << 2; \
            pf[_i] = *(const float4*)&A[(size_t)(bm + _r) * EE + (kc) * 64 + _c4]; \
        } \
    } while (0)

#define STORE_A() do { \
        _Pragma("unroll") \
        for (int _i = 0; _i < 4; _i++) { \
            int _idx = tid + _i * 512; \
            int _r = _idx >> 4, _c4 = (_idx & 15) << 2; \
            uint32_t _off = _r * PITCHB + _c4 * 2; \
            uint2 _s0 = splitpack(pf[_i].x, pf[_i].y); \
            uint2 _s1 = splitpack(pf[_i].z, pf[_i].w); \
            asm volatile("st.shared.v2.b32 [%0], {%1,%2};" :: "r"(AhU + _off), "r"(_s0.x), "r"(_s1.x) : "memory"); \
            asm volatile("st.shared.v2.b32 [%0], {%1,%2};" :: "r"(AlU + _off), "r"(_s0.y), "r"(_s1.y) : "memory"); \
        } \
    } while (0)

    ISSUE_B(0, 0);
    LOAD_A(0);
    STORE_A();
    asm volatile("cp.async.wait_group 0;" ::: "memory");
    __syncthreads();

    for (int kc = 0; kc < 4; kc++) {
        int s = kc & 1;
        if (kc < 3) {
            ISSUE_B(kc + 1, s ^ 1);
            LOAD_A(kc + 1);
        }
        uint32_t BhU = BsU + s * BSTAGE;
        uint32_t BlU = BhU + TILEB;
#pragma unroll
        for (int ks = 0; ks < 4; ks++) {
            int cbb = ks * 32;
            unsigned ah[2][4], bh[4][2], bx[4][2], tmp[4];
#pragma unroll
            for (int mi = 0; mi < 2; mi++) {
                int rb = wm * 32 + mi * 16;
                ldsm4(ah[mi], AhU + (rb + a_roff) * PITCHB + cbb + a_coff);
            }
#pragma unroll
            for (int p = 0; p < 2; p++) {
                int nb = wn * 32 + p * 16;
                ldsm4(tmp, BhU + (nb + b_roff) * PITCHB + cbb + b_coff);
                bh[2*p][0] = tmp[0]; bh[2*p][1] = tmp[1];
                bh[2*p+1][0] = tmp[2]; bh[2*p+1][1] = tmp[3];
            }
#pragma unroll
            for (int mi = 0; mi < 2; mi++)
#pragma unroll
                for (int ni = 0; ni < 4; ni++) mma16816(acc[mi][ni], ah[mi], bh[ni]);
#pragma unroll
            for (int p = 0; p < 2; p++) {
                int nb = wn * 32 + p * 16;
                ldsm4(tmp, BlU + (nb + b_roff) * PITCHB + cbb + b_coff);
                bx[2*p][0] = tmp[0]; bx[2*p][1] = tmp[1];
                bx[2*p+1][0] = tmp[2]; bx[2*p+1][1] = tmp[3];
            }
#pragma unroll
            for (int mi = 0; mi < 2; mi++)
#pragma unroll
                for (int ni = 0; ni < 4; ni++) mma16816(acc[mi][ni], ah[mi], bx[ni]);
#pragma unroll
            for (int mi = 0; mi < 2; mi++) {
                int rb = wm * 32 + mi * 16;
                ldsm4(ah[mi], AlU + (rb + a_roff) * PITCHB + cbb + a_coff);
            }
#pragma unroll
            for (int mi = 0; mi < 2; mi++)
#pragma unroll
                for (int ni = 0; ni < 4; ni++) mma16816(acc[mi][ni], ah[mi], bh[ni]);
        }
        __syncthreads();
        if (kc < 3) {
            STORE_A();
            asm volatile("cp.async.wait_group 0;" ::: "memory");
            __syncthreads();
        }
    }

    // ---- epilogue ----
    int g = lane >> 2, tc = lane & 3;
    if (epi == EPI_QZ) {
        int n = bm >> 12;
        int h = (bn + wn * 32) >> 5;
        const float* ksp = g_KV + (size_t)(n * HH + h) * 1056 + 1024;
        int rbblk = bm >> 7;
#pragma unroll
        for (int mi = 0; mi < 2; mi++) {
            int r0 = bm + wm * 32 + mi * 16 + g;
            int r1 = r0 + 8;
            float mv0 = mask_val(mask, r0), mv1 = mask_val(mask, r1);
            float cb[4][4];
            float p0 = 0.f, p1 = 0.f;
#pragma unroll
            for (int ni = 0; ni < 4; ni++) {
                int col = bn + wn * 32 + ni * 8 + tc * 2;
                int d = ni * 8 + tc * 2;
                float b0 = bias[col], b1 = bias[col + 1];
                float c0 = acc[mi][ni][0] + b0, c1 = acc[mi][ni][1] + b1;
                float c2 = acc[mi][ni][2] + b0, c3 = acc[mi][ni][3] + b1;
                c0 = (c0 > 0.f ? c0 + 1.f : expf(c0)) * mv0;
                c1 = (c1 > 0.f ? c1 + 1.f : expf(c1)) * mv0;
                c2 = (c2 > 0.f ? c2 + 1.f : expf(c2)) * mv1;
                c3 = (c3 > 0.f ? c3 + 1.f : expf(c3)) * mv1;
                float k0 = ksp[d], k1 = ksp[d + 1];
                p0 += c0 * k0 + c1 * k1;
                p1 += c2 * k0 + c3 * k1;
                cb[ni][0] = c0; cb[ni][1] = c1; cb[ni][2] = c2; cb[ni][3] = c3;
            }
            p0 += __shfl_xor_sync(0xffffffffu, p0, 1);
            p0 += __shfl_xor_sync(0xffffffffu, p0, 2);
            p1 += __shfl_xor_sync(0xffffffffu, p1, 1);
            p1 += __shfl_xor_sync(0xffffffffu, p1, 2);
            float z0 = 1.f / (p0 + EPSV), z1 = 1.f / (p1 + EPSV);
            int lr0 = wm * 32 + mi * 16 + g, lr1 = lr0 + 8;
#pragma unroll
            for (int ni = 0; ni < 4; ni++) {
                int col = bn + wn * 32 + ni * 8 + tc * 2;
                int kcb = col >> 6, cc = col & 63;
                uint2 s0 = splitpack(cb[ni][0] * z0, cb[ni][1] * z0);
                uint2 s1 = splitpack(cb[ni][2] * z1, cb[ni][3] * z1);
                ushortT* base = g_Qsp + (size_t)rbblk * 73728 + kcb * 18432 + cc;
                *(unsigned*)(base + lr0 * 72) = s0.x;
                *(unsigned*)(base + lr0 * 72 + 9216) = s0.y;
                *(unsigned*)(base + lr1 * 72) = s1.x;
                *(unsigned*)(base + lr1 * 72 + 9216) = s1.y;
            }
        }
    } else {
#pragma unroll
        for (int mi = 0; mi < 2; mi++) {
            int r0 = bm + wm * 32 + mi * 16 + g;
            int r1 = r0 + 8;
            float mv0 = mask_val(mask, r0), mv1 = mask_val(mask, r1);
#pragma unroll
            for (int ni = 0; ni < 4; ni++) {
                int col = bn + wn * 32 + ni * 8 + tc * 2;
                float c0 = acc[mi][ni][0], c1 = acc[mi][ni][1];
                float c2 = acc[mi][ni][2], c3 = acc[mi][ni][3];
                float b0 = bias[col], b1 = bias[col + 1];
                if (epi == EPI_FEAT) {
                    c0 += b0; c1 += b1; c2 += b0; c3 += b1;
                    c0 = (c0 > 0.f ? c0 + 1.f : expf(c0)) * mv0;
                    c1 = (c1 > 0.f ? c1 + 1.f : expf(c1)) * mv0;
                    c2 = (c2 > 0.f ? c2 + 1.f : expf(c2)) * mv1;
                    c3 = (c3 > 0.f ? c3 + 1.f : expf(c3)) * mv1;
                } else {  // EPI_VPROJ
                    c0 = (c0 + b0) * mv0 * scale; c1 = (c1 + b1) * mv0 * scale;
                    c2 = (c2 + b0) * mv1 * scale; c3 = (c3 + b1) * mv1 * scale;
                }
                *(float2*)&C[(size_t)r0 * EE + col] = make_float2(c0, c1);
                *(float2*)&C[(size_t)r1 * EE + col] = make_float2(c2, c3);
            }
        }
    }
#undef ISSUE_B
#undef LOAD_A
#undef STORE_A
}

// ================= final GEMM: both operands pre-split (pure cp.async + mma) =================
#define PSTAGE 36864                 // hi|lo per chunk
#define SMEM_PRE (4*PSTAGE)          // A x2 stages + B x2 stages = 147456

__global__ void __launch_bounds__(512) tgemm_pre(float* __restrict__ C) {
    uint32_t AsU = smem_u32(dyn_smem);
    uint32_t BsU = AsU + 2 * PSTAGE;

    int tid = threadIdx.x, wid = tid >> 5, lane = tid & 31;
    int wm = wid >> 2, wn = wid & 3;
    int bm = blockIdx.y * 128, bn = blockIdx.x * 128;
    const ushortT* A = g_Qsp + (size_t)(bm >> 7) * 73728;
    const ushortT* B = g_UTsp + (size_t)(bm >> 12) * MATU;

    int lmat = lane >> 3, lrow = lane & 7;
    int a_roff = ((lmat & 1) ? 8 : 0) + lrow;
    int a_coff = (lmat & 2) ? 16 : 0;
    int b_roff = ((lmat & 2) ? 8 : 0) + lrow;
    int b_coff = (lmat & 1) ? 16 : 0;

    float acc[2][4][4];
#pragma unroll
    for (int mi = 0; mi < 2; mi++)
#pragma unroll
        for (int ni = 0; ni < 4; ni++)
#pragma unroll
            for (int j = 0; j < 4; j++) acc[mi][ni][j] = 0.f;

#define ISSUE2(kc, st) do { \
        const char* _as = (const char*)(A + (size_t)(kc) * 18432); \
        const char* _bs = (const char*)(B + (size_t)(blockIdx.x * 4 + (kc)) * 18432); \
        uint32_t _ad = AsU + (st) * PSTAGE, _bd = BsU + (st) * PSTAGE; \
        _Pragma("unroll") \
        for (int _j = 0; _j < 5; _j++) { \
            int _id = tid + _j * 512; \
            if (_id < 2304) { \
                asm volatile("cp.async.cg.shared.global [%0], [%1], 16;" \
                    :: "r"(_ad + _id * 16), "l"(_as + _id * 16)); \
                asm volatile("cp.async.cg.shared.global [%0], [%1], 16;" \
                    :: "r"(_bd + _id * 16), "l"(_bs + _id * 16)); \
            } \
        } \
        asm volatile("cp.async.commit_group;" ::: "memory"); \
    } while (0)

    ISSUE2(0, 0);
    ISSUE2(1, 1);

    for (int kc = 0; kc < 4; kc++) {
        int st = kc & 1;
        if (kc == 3) asm volatile("cp.async.wait_group 0;" ::: "memory");
        else         asm volatile("cp.async.wait_group 1;" ::: "memory");
        __syncthreads();
        uint32_t AhU = AsU + st * PSTAGE, AlU = AhU + TILEB;
        uint32_t BhU = BsU + st * PSTAGE, BlU = BhU + TILEB;
#pragma unroll
        for (int ks = 0; ks < 4; ks++) {
            int cbb = ks * 32;
            unsigned ah[2][4], bh[4][2], bx[4][2], tmp[4];
#pragma unroll
            for (int mi = 0; mi < 2; mi++) {
                int rb = wm * 32 + mi * 16;
                ldsm4(ah[mi], AhU + (rb + a_roff) * PITCHB + cbb + a_coff);
            }
#pragma unroll
            for (int p = 0; p < 2; p++) {
                int nb = wn * 32 + p * 16;
                ldsm4(tmp, BhU + (nb + b_roff) * PITCHB + cbb + b_coff);
                bh[2*p][0] = tmp[0]; bh[2*p][1] = tmp[1];
                bh[2*p+1][0] = tmp[2]; bh[2*p+1][1] = tmp[3];
            }
#pragma unroll
            for (int mi = 0; mi < 2; mi++)
#pragma unroll
                for (int ni = 0; ni < 4; ni++) mma16816(acc[mi][ni], ah[mi], bh[ni]);
#pragma unroll
            for (int p = 0; p < 2; p++) {
                int nb = wn * 32 + p * 16;
                ldsm4(tmp, BlU + (nb + b_roff) * PITCHB + cbb + b_coff);
                bx[2*p][0] = tmp[0]; bx[2*p][1] = tmp[1];
                bx[2*p+1][0] = tmp[2]; bx[2*p+1][1] = tmp[3];
            }
#pragma unroll
            for (int mi = 0; mi < 2; mi++)
#pragma unroll
                for (int ni = 0; ni < 4; ni++) mma16816(acc[mi][ni], ah[mi], bx[ni]);
#pragma unroll
            for (int mi = 0; mi < 2; mi++) {
                int rb = wm * 32 + mi * 16;
                ldsm4(ah[mi], AlU + (rb + a_roff) * PITCHB + cbb + a_coff);
            }
#pragma unroll
            for (int mi = 0; mi < 2; mi++)
#pragma unroll
                for (int ni = 0; ni < 4; ni++) mma16816(acc[mi][ni], ah[mi], bh[ni]);
        }
        __syncthreads();
        if (kc < 2) ISSUE2(kc + 2, st);
    }

    int g = lane >> 2, tc = lane & 3;
#pragma unroll
    for (int mi = 0; mi < 2; mi++) {
        int r0 = bm + wm * 32 + mi * 16 + g;
        int r1 = r0 + 8;
#pragma unroll
        for (int ni = 0; ni < 4; ni++) {
            int col = bn + wn * 32 + ni * 8 + tc * 2;
            *(float2*)&C[(size_t)r0 * EE + col] = make_float2(acc[mi][ni][0], acc[mi][ni][1]);
            *(float2*)&C[(size_t)r1 * EE + col] = make_float2(acc[mi][ni][2], acc[mi][ni][3]);
        }
    }
#undef ISSUE2
}

// ---------------- KV aggregation: register-tiled partial sums ----------------
__global__ __launch_bounds__(256) void kv_partial() {
    int nh = blockIdx.x;
    int n = nh >> 3, h = nh & 7;
    int chunk = blockIdx.y;
    __shared__ float Ks[64][32];
    __shared__ float Vs[64][32];
    __shared__ float red[4][1056];
    int tid = threadIdx.x;
    int grp = tid >> 6;
    int gt = tid & 63;
    int dg = gt >> 3;
    int vg = gt & 7;
    float acc[4][4] = {};
    float ks[4] = {};
    int s0base = chunk * CHS;
    const float* Kp = g_Kf + (size_t)n * SS * EE + h * DD;
    const float* Vp = g_Vm + (size_t)n * SS * EE + h * DD;
    for (int s0 = 0; s0 < CHS; s0 += 64) {
#pragma unroll
        for (int r = 0; r < 2; r++) {
            int idx = tid + r * 256;
            int row = idx >> 3, c = (idx & 7) * 4;
            size_t gidx = (size_t)(s0base + s0 + row) * EE + c;
            *(float4*)&Ks[row][c] = *(const float4*)&Kp[gidx];
            *(float4*)&Vs[row][c] = *(const float4*)&Vp[gidx];
        }
        __syncthreads();
#pragma unroll
        for (int si = 0; si < 16; si++) {
            int s = grp * 16 + si;
            float4 kk = *(const float4*)&Ks[s][dg * 4];
            float4 vv = *(const float4*)&Vs[s][vg * 4];
            float ka[4] = {kk.x, kk.y, kk.z, kk.w};
            float va[4] = {vv.x, vv.y, vv.z, vv.w};
#pragma unroll
            for (int i = 0; i < 4; i++) {
                ks[i] += ka[i];
#pragma unroll
                for (int j = 0; j < 4; j++) acc[i][j] += ka[i] * va[j];
            }
        }
        __syncthreads();
    }
#pragma unroll
    for (int i = 0; i < 4; i++)
#pragma unroll
        for (int j = 0; j < 4; j++)
            red[grp][(dg * 4 + i) * 32 + vg * 4 + j] = acc[i][j];
    if (vg == 0) {
#pragma unroll
        for (int i = 0; i < 4; i++) red[grp][1024 + dg * 4 + i] = ks[i];
    }
    __syncthreads();
    float* P = g_part + ((size_t)chunk * 64 + nh) * 1056;
    for (int i = tid; i < 1056; i += 256)
        P[i] = red[0][i] + red[1][i] + red[2][i] + red[3][i];
}

__global__ void kv_reduce() {
    int nh = blockIdx.x;
    for (int i = threadIdx.x; i < 1056; i += blockDim.x) {
        float s = 0;
        for (int c = 0; c < NCHUNK; c++) s += g_part[((size_t)c * 64 + nh) * 1056 + i];
        g_KV[(size_t)nh * 1056 + i] = s;
    }
}

// ---------------- make UT directly in split-bf16 tiled layout ----------------
__global__ __launch_bounds__(256) void make_ut(const float* __restrict__ Wm) {
    int nh = blockIdx.x; int n = nh >> 3, h = nh & 7;
    __shared__ float KVs[32][32];
    int tid = threadIdx.x;
    for (int i = tid; i < 1024; i += 256) KVs[i >> 5][i & 31] = g_KV[(size_t)nh * 1056 + i];
    __syncthreads();
    int ep = tid;
    float w[32];
#pragma unroll
    for (int v = 0; v < 32; v++) w[v] = Wm[(size_t)ep * EE + h * DD + v];
    ushortT* dsth = g_UTsp + (size_t)n * MATU
                  + ((size_t)((ep >> 7) * 4 + (h >> 1))) * 18432
                  + (ep & 127) * 72 + (h & 1) * 32;
#pragma unroll
    for (int d2 = 0; d2 < 32; d2++) {
        float a = 0;
#pragma unroll
        for (int v = 0; v < 32; v++) a += KVs[d2][v] * w[v];
        a *= (float)SS;
        __nv_bfloat16 hb = __float2bfloat16(a);
        float hr = __bfloat162float(hb);
        __nv_bfloat16 lb = __float2bfloat16(a - hr);
        dsth[d2] = __bfloat16_as_ushort(hb);
        dsth[9216 + d2] = __bfloat16_as_ushort(lb);
    }
}

// ---------------- launch ----------------
extern "C" void kernel_launch(void* const* d_in, const int* in_sizes, int n_in,
                              void* d_out, int out_size) {
    const float* q  = (const float*)d_in[0];
    const float* k  = (const float*)d_in[1];
    const float* v  = (const float*)d_in[2];
    const void*  qm = d_in[3];
    const void*  km = d_in[4];
    const float* Wq = (const float*)d_in[5];
    const float* bq = (const float*)d_in[6];
    const float* Wk = (const float*)d_in[7];
    const float* bk = (const float*)d_in[8];
    const float* Wv = (const float*)d_in[9];
    const float* bv = (const float*)d_in[10];
    const float* Wm = (const float*)d_in[11];
    float* out = (float*)d_out;

    float *Kf, *Vm;
    ushortT *Wsp;
    cudaGetSymbolAddress((void**)&Kf, g_Kf);
    cudaGetSymbolAddress((void**)&Vm, g_Vm);
    cudaGetSymbolAddress((void**)&Wsp, g_Wsp);

    cudaFuncSetAttribute(tgemm, cudaFuncAttributeMaxDynamicSharedMemorySize, SMEM_SZ);
    cudaFuncSetAttribute(tgemm_pre, cudaFuncAttributeMaxDynamicSharedMemorySize, SMEM_PRE);

    detect_mask_kernel<<<1, 256>>>((const unsigned int*)km, 2048);
    split_w3<<<dim3(8, 3), 256>>>(Wq, Wk, Wv);

    // K and V projections (fused, z = 2)
    tgemm<<<dim3(2, NTOK / 128, 2), 512, SMEM_SZ>>>(
        k, v, Wsp + MATU, MATU,
        bk, bv, Kf, Vm,
        EPI_FEAT, EPI_VPROJ,
        km, 1.f / (float)SS);

    kv_partial<<<dim3(64, NCHUNK), 256>>>();
    kv_reduce<<<64, 256>>>();
    make_ut<<<64, 256>>>(Wm);

    // Q projection with Z folded; writes split-tiled g_Qsp
    tgemm<<<dim3(2, NTOK / 128, 1), 512, SMEM_SZ>>>(
        q, q, Wsp, 0,
        bq, bq, out, out,
        EPI_QZ, EPI_QZ,
        qm, 1.f);

    // final: (Qf*Z) @ UT[n]^T, both operands pre-split
    tgemm_pre<<<dim3(2, NTOK / 128), 512, SMEM_PRE>>>(out);
}